// round 11
// baseline (speedup 1.0000x reference)
#include <cuda_runtime.h>
#include <cstdint>
#include <cstddef>

#define N_NODES  100000
#define N_EDGES  3200000
#define FEAT     128
#define NUM_RELS 16
#define NUM_BASES 8
#define KTOT     (NUM_BASES * FEAT)   // 1024

#define NBLK_SCAN 196                 // 196 * 512 = 100352 >= N_NODES

// Scratch (static device globals — no runtime allocation allowed).
__device__ float g_agg[(size_t)N_NODES * NUM_BASES * FEAT];  // 410 MB, tf32-rounded
__device__ float g_bt [(size_t)FEAT * KTOT];                 // 512 KB: Bt[n][k], tf32
__device__ int   g_deg [N_NODES];
__device__ int   g_off [N_NODES];
__device__ int   g_cur [N_NODES];
__device__ int   g_pack[N_EDGES];                            // (et<<17)|src
__device__ int   g_part [NBLK_SCAN];
__device__ int   g_partx[NBLK_SCAN];
__device__ int   g_idx64;

// ---------------------------------------------------------------------------
// Helpers
// ---------------------------------------------------------------------------
typedef unsigned long long u64;

__device__ __forceinline__ u64 pack2(float lo, float hi) {
    u64 r; asm("mov.b64 %0, {%1, %2};" : "=l"(r) : "f"(lo), "f"(hi)); return r;
}
__device__ __forceinline__ u64 dup2(float v) {
    u64 r; asm("mov.b64 %0, {%1, %1};" : "=l"(r) : "f"(v)); return r;
}
__device__ __forceinline__ void fma2(u64& acc, u64 a, u64 b) {
    asm("fma.rn.f32x2 %0, %1, %2, %0;" : "+l"(acc) : "l"(a), "l"(b));
}
__device__ __forceinline__ float2 unpack2(u64 v) {
    float lo, hi; asm("mov.b64 {%0, %1}, %2;" : "=f"(lo), "=f"(hi) : "l"(v));
    return make_float2(lo, hi);
}
__device__ __forceinline__ float f2tf32f(float f) {
    uint32_t r; asm("cvt.rna.tf32.f32 %0, %1;" : "=r"(r) : "f"(f));
    return __uint_as_float(r);
}
__device__ __forceinline__ void mma_tf32(float* c,
                                         uint32_t a0, uint32_t a1, uint32_t a2, uint32_t a3,
                                         uint32_t b0, uint32_t b1) {
    asm volatile("mma.sync.aligned.m16n8k8.row.col.f32.tf32.tf32.f32 "
                 "{%0,%1,%2,%3}, {%4,%5,%6,%7}, {%8,%9}, {%0,%1,%2,%3};"
                 : "+f"(c[0]), "+f"(c[1]), "+f"(c[2]), "+f"(c[3])
                 : "r"(a0), "r"(a1), "r"(a2), "r"(a3), "r"(b0), "r"(b1));
}
__device__ __forceinline__ uint32_t smem_u32(const void* p) {
    uint32_t a;
    asm("{ .reg .u64 t; cvta.to.shared.u64 t, %1; cvt.u32.u64 %0, t; }"
        : "=r"(a) : "l"(p));
    return a;
}
__device__ __forceinline__ void cpa16(uint32_t dst, const void* src, uint32_t sz) {
    asm volatile("cp.async.cg.shared.global [%0], [%1], 16, %2;"
                 :: "r"(dst), "l"(src), "r"(sz) : "memory");
}
#define CP_COMMIT() asm volatile("cp.async.commit_group;" ::: "memory")
#define CP_WAIT1()  asm volatile("cp.async.wait_group 1;" ::: "memory")

// ---------------------------------------------------------------------------
// Probe: int64 vs int32 indices (parallel: 1024 loads, 1 block)
// ---------------------------------------------------------------------------
__global__ void probe_kernel(const void* src) {
    __shared__ int bad;
    if (threadIdx.x == 0) bad = 0;
    __syncthreads();
    long long v = ((const long long*)src)[threadIdx.x];
    if (v < 0 || v >= (long long)N_NODES) bad = 1;
    __syncthreads();
    if (threadIdx.x == 0) g_idx64 = bad ? 0 : 1;
}

__device__ __forceinline__ int load_idx(const void* p, int e, int idx64) {
    return idx64 ? (int)((const long long*)p)[e] : ((const int*)p)[e];
}

// ---------------------------------------------------------------------------
// Bt[n][k] = tf32(weight[k/128][k%128][n])   (transposed B for out_gemm)
// ---------------------------------------------------------------------------
__global__ __launch_bounds__(256) void prep_bt(const float* __restrict__ weight) {
    int idx = blockIdx.x * 256 + threadIdx.x;       // 128*1024 = 131072
    if (idx >= FEAT * KTOT) return;
    int n = idx >> 10, k = idx & 1023;
    int b = k >> 7, kin = k & 127;
    g_bt[idx] = f2tf32f(weight[((size_t)b * FEAT + kin) * FEAT + n]);
}

// ---------------------------------------------------------------------------
// CSR build
// ---------------------------------------------------------------------------
__global__ __launch_bounds__(256) void zero_deg() {
    int i = blockIdx.x * 256 + threadIdx.x;
    if (i < N_NODES) g_deg[i] = 0;
}

__global__ __launch_bounds__(256) void count_deg(const void* dstp) {
    int e = blockIdx.x * 256 + threadIdx.x;
    if (e >= N_EDGES) return;
    int d = load_idx(dstp, e, g_idx64);
    atomicAdd(&g_deg[d], 1);
}

__global__ __launch_bounds__(256) void scan1() {
    __shared__ int wsum[8];
    int t = threadIdx.x, blk = blockIdx.x;
    int i0 = blk * 512 + 2 * t, i1 = i0 + 1;
    int s = (i0 < N_NODES ? g_deg[i0] : 0) + (i1 < N_NODES ? g_deg[i1] : 0);
#pragma unroll
    for (int o = 16; o > 0; o >>= 1) s += __shfl_down_sync(0xffffffffu, s, o);
    if ((t & 31) == 0) wsum[t >> 5] = s;
    __syncthreads();
    if (t == 0) {
        int tot = 0;
#pragma unroll
        for (int w = 0; w < 8; w++) tot += wsum[w];
        g_part[blk] = tot;
    }
}

__global__ __launch_bounds__(256) void scan2() {
    __shared__ int sh[256];
    int t = threadIdx.x;
    int v = (t < NBLK_SCAN) ? g_part[t] : 0;
    int orig = v;
    sh[t] = v;
    __syncthreads();
    for (int o = 1; o < 256; o <<= 1) {
        int u = (t >= o) ? sh[t - o] : 0;
        __syncthreads();
        sh[t] += u;
        __syncthreads();
    }
    if (t < NBLK_SCAN) g_partx[t] = sh[t] - orig;
}

__global__ __launch_bounds__(256) void scan3() {
    __shared__ int wsum[8], woff[8];
    int t = threadIdx.x, blk = blockIdx.x;
    int lane = t & 31, wid = t >> 5;
    int i0 = blk * 512 + 2 * t, i1 = i0 + 1;
    int d0 = (i0 < N_NODES ? g_deg[i0] : 0);
    int d1 = (i1 < N_NODES ? g_deg[i1] : 0);
    int s = d0 + d1;
    int v = s;
#pragma unroll
    for (int o = 1; o < 32; o <<= 1) {
        int u = __shfl_up_sync(0xffffffffu, v, o);
        if (lane >= o) v += u;
    }
    if (lane == 31) wsum[wid] = v;
    __syncthreads();
    if (t < 8) {
        int p = 0;
        for (int j = 0; j < t; j++) p += wsum[j];
        woff[t] = p;
    }
    __syncthreads();
    int excl = v - s + woff[wid] + g_partx[blk];
    if (i0 < N_NODES) { g_off[i0] = excl;      g_cur[i0] = excl;      }
    if (i1 < N_NODES) { g_off[i1] = excl + d0; g_cur[i1] = excl + d0; }
}

__global__ __launch_bounds__(256) void fill_csr(const void* srcp,
                                                const void* dstp,
                                                const void* etp) {
    int e = blockIdx.x * 256 + threadIdx.x;
    if (e >= N_EDGES) return;
    int idx64 = g_idx64;
    int s  = load_idx(srcp, e, idx64);
    int d  = load_idx(dstp, e, idx64);
    int et = load_idx(etp,  e, idx64);
    int pos = atomicAdd(&g_cur[d], 1);
    g_pack[pos] = (et << 17) | s;
}

// ---------------------------------------------------------------------------
// Aggregate: one warp per dst node; f32x2 accumulate; tf32-round on store.
// ---------------------------------------------------------------------------
__global__ __launch_bounds__(256) void aggregate(const float* __restrict__ x,
                                                 const float* __restrict__ w_comp) {
    __shared__ float cw[NUM_RELS * NUM_BASES];
    if (threadIdx.x < NUM_RELS * NUM_BASES)
        cw[threadIdx.x] = w_comp[threadIdx.x];
    __syncthreads();

    const int node = blockIdx.x * 8 + (threadIdx.x >> 5);
    const int lane = threadIdx.x & 31;
    if (node >= N_NODES) return;

    const int beg = g_off[node];
    const int cnt = g_deg[node];
    const float4* x4 = (const float4*)x;

    u64 acc[NUM_BASES][2];
#pragma unroll
    for (int b = 0; b < NUM_BASES; b++) { acc[b][0] = 0ull; acc[b][1] = 0ull; }

    for (int b0 = 0; b0 < cnt; b0 += 32) {
        int pk = (b0 + lane < cnt) ? g_pack[beg + b0 + lane] : 0;
        int m = cnt - b0;
        if (m > 32) m = 32;
#pragma unroll 4
        for (int j = 0; j < m; j++) {
            int p = __shfl_sync(0xffffffffu, pk, j);
            int src = p & 0x1FFFF;
            int et  = p >> 17;
            float4 xv = x4[(size_t)src * 32 + lane];
            u64 xlo = pack2(xv.x, xv.y);
            u64 xhi = pack2(xv.z, xv.w);
#pragma unroll
            for (int b = 0; b < NUM_BASES; b++) {
                u64 c2 = dup2(cw[et * NUM_BASES + b]);
                fma2(acc[b][0], c2, xlo);
                fma2(acc[b][1], c2, xhi);
            }
        }
    }

    float4* ag = (float4*)g_agg + (size_t)node * NUM_BASES * 32 + lane;
#pragma unroll
    for (int b = 0; b < NUM_BASES; b++) {
        float2 lo = unpack2(acc[b][0]);
        float2 hi = unpack2(acc[b][1]);
        __stcs(ag + b * 32, make_float4(f2tf32f(lo.x), f2tf32f(lo.y),
                                        f2tf32f(hi.x), f2tf32f(hi.y)));
    }
}

// ---------------------------------------------------------------------------
// out[100000 x 128] = agg[100000 x 1024] @ Bt^T + bias  via tf32 mma.sync.
// BM=128, BN=128, BK=32; 256 thr = 8 warps (4M x 2N); warp tile 32x64.
// cp.async 3-stage pipeline, one __syncthreads per K-iteration.
// As/Bs: [row][k] pitch 36 floats -> conflict-free fragment LDS.
// ---------------------------------------------------------------------------
#define GP 36
#define BUF_WORDS (128 * GP)                      // 4608 floats per A/B buffer
#define NKIT      (KTOT / 32)                     // 32 K-iterations
static constexpr size_t GEMM_SMEM = (size_t)3 * 2 * BUF_WORDS * 4;  // 110592 B

__global__ __launch_bounds__(256, 2) void out_gemm(const float* __restrict__ bias,
                                                   float* __restrict__ out) {
    extern __shared__ float dsm[];
    __shared__ float bsm[128];

    const int tid    = threadIdx.x;
    const int wid    = tid >> 5;
    const int lane   = tid & 31;
    const int warp_m = wid & 3;
    const int warp_n = wid >> 2;
    const int grp    = lane >> 2;
    const int tig    = lane & 3;
    const int m0     = blockIdx.x * 128;

    if (tid < 128) bsm[tid] = bias[tid];

    float acc[2][8][4];
#pragma unroll
    for (int i = 0; i < 2; i++)
#pragma unroll
        for (int j = 0; j < 8; j++)
#pragma unroll
            for (int q = 0; q < 4; q++) acc[i][j][q] = 0.f;

    const int lrow = tid >> 1;             // 0..127 (A m-row / B n-row)
    const int lkq  = (tid & 1) * 16;       // k sub-chunk 0 or 16
    const bool aok = (m0 + lrow) < N_NODES;
    const uint32_t a_sz = aok ? 16u : 0u;  // cp.async zero-fill for OOB rows
    const float* aptr = g_agg + (size_t)(m0 + lrow) * KTOT + lkq;
    const float* bptr = g_bt  + (size_t)lrow * KTOT + lkq;

    const uint32_t sbase  = smem_u32(dsm);
    const uint32_t th_off = (uint32_t)(lrow * GP + lkq) * 4u;

    // ---- Prologue: prefetch stages 0 and 1 ----
#pragma unroll
    for (int is = 0; is < 2; is++) {
        uint32_t ad = sbase + (uint32_t)is * 2u * BUF_WORDS * 4u + th_off;
        uint32_t bd = ad + BUF_WORDS * 4u;
        const float* ap = aptr + is * 32;
        const float* bp = bptr + is * 32;
#pragma unroll
        for (int q = 0; q < 4; q++) {
            cpa16(ad + q * 16u, ap + q * 4, a_sz);
            cpa16(bd + q * 16u, bp + q * 4, 16u);
        }
        CP_COMMIT();
    }

    for (int i = 0; i < NKIT; i++) {
        CP_WAIT1();            // stage i's group complete (i+1 may pend)
        __syncthreads();       // data visible to all + stage (i-1) compute done

        // ---- Prefetch stage i+2 (buffer (i+2)%3, last used by compute i-1) ----
        int is = i + 2;
        if (is < NKIT) {
            int sb = is - (is / 3) * 3;
            uint32_t ad = sbase + (uint32_t)sb * 2u * BUF_WORDS * 4u + th_off;
            uint32_t bd = ad + BUF_WORDS * 4u;
            const float* ap = aptr + is * 32;
            const float* bp = bptr + is * 32;
#pragma unroll
            for (int q = 0; q < 4; q++) {
                cpa16(ad + q * 16u, ap + q * 4, a_sz);
                cpa16(bd + q * 16u, bp + q * 4, 16u);
            }
        }
        CP_COMMIT();           // unconditional: keeps wait-distance invariant

        // ---- Compute on stage i (buffer i%3) ----
        int cb = i - (i / 3) * 3;
        const float* As = dsm + (size_t)cb * 2 * BUF_WORDS;
        const float* Bs = As + BUF_WORDS;

#pragma unroll
        for (int ks = 0; ks < 4; ks++) {
            const int k0 = ks * 8;
            uint32_t bf[8][2];
#pragma unroll
            for (int j = 0; j < 8; j++) {
                const float* bp = Bs + (warp_n * 64 + j * 8 + grp) * GP + k0 + tig;
                bf[j][0] = __float_as_uint(bp[0]);
                bf[j][1] = __float_as_uint(bp[4]);
            }
#pragma unroll
            for (int ii = 0; ii < 2; ii++) {
                const float* ap = As + (warp_m * 32 + ii * 16 + grp) * GP + k0 + tig;
                uint32_t a0 = __float_as_uint(ap[0]);
                uint32_t a1 = __float_as_uint(ap[8 * GP]);
                uint32_t a2 = __float_as_uint(ap[4]);
                uint32_t a3 = __float_as_uint(ap[8 * GP + 4]);
#pragma unroll
                for (int j = 0; j < 8; j++)
                    mma_tf32(acc[ii][j], a0, a1, a2, a3, bf[j][0], bf[j][1]);
            }
        }
    }

#pragma unroll
    for (int i = 0; i < 2; i++) {
        int row_lo = m0 + warp_m * 32 + i * 16 + grp;
        int row_hi = row_lo + 8;
#pragma unroll
        for (int j = 0; j < 8; j++) {
            int col = warp_n * 64 + j * 8 + 2 * tig;
            if (row_lo < N_NODES)
                *(float2*)(out + (size_t)row_lo * FEAT + col) =
                    make_float2(acc[i][j][0] + bsm[col],
                                acc[i][j][1] + bsm[col + 1]);
            if (row_hi < N_NODES)
                *(float2*)(out + (size_t)row_hi * FEAT + col) =
                    make_float2(acc[i][j][2] + bsm[col],
                                acc[i][j][3] + bsm[col + 1]);
        }
    }
}

// ---------------------------------------------------------------------------
// Launch
// ---------------------------------------------------------------------------
extern "C" void kernel_launch(void* const* d_in, const int* in_sizes, int n_in,
                              void* d_out, int out_size) {
    const float* x      = (const float*)d_in[0];
    const float* weight = (const float*)d_in[1];
    const float* w_comp = (const float*)d_in[2];
    const float* h_bias = (const float*)d_in[3];
    const void*  src    = d_in[4];
    const void*  dst    = d_in[5];
    const void*  etyp   = d_in[6];
    float*       out    = (float*)d_out;

    cudaFuncSetAttribute(out_gemm, cudaFuncAttributeMaxDynamicSharedMemorySize,
                         (int)GEMM_SMEM);

    probe_kernel<<<1, 1024>>>(src);
    prep_bt<<<(FEAT * KTOT + 255) / 256, 256>>>(weight);

    // CSR by destination
    zero_deg<<<(N_NODES + 255) / 256, 256>>>();
    count_deg<<<(N_EDGES + 255) / 256, 256>>>(dst);
    scan1<<<NBLK_SCAN, 256>>>();
    scan2<<<1, 256>>>();
    scan3<<<NBLK_SCAN, 256>>>();
    fill_csr<<<(N_EDGES + 255) / 256, 256>>>(src, dst, etyp);

    // Basis-weighted aggregation (tf32-rounded output)
    aggregate<<<(N_NODES + 7) / 8, 256>>>(x, w_comp);

    // Fused transform + bias (tf32 tensor-core GEMM, cp.async pipelined)
    out_gemm<<<(N_NODES + 127) / 128, 256, GEMM_SMEM>>>(h_bias, out);
}

// round 12
// speedup vs baseline: 1.3202x; 1.3202x over previous
#include <cuda_runtime.h>
#include <cuda_fp16.h>
#include <cstdint>
#include <cstddef>

#define N_NODES  100000
#define N_EDGES  3200000
#define FEAT     128
#define NUM_RELS 16
#define NUM_BASES 8
#define KTOT     (NUM_BASES * FEAT)   // 1024

#define NBLK_SCAN 196                 // 196 * 512 = 100352 >= N_NODES

// Scratch (static device globals — no runtime allocation allowed).
__device__ __half g_aggh[(size_t)N_NODES * KTOT];   // 205 MB: agg[d][b*128+k], fp16
__device__ __half g_bth [(size_t)KTOT * FEAT];      // 256 KB: B[k][n] = weight flat, fp16
__device__ int    g_deg [N_NODES];
__device__ int    g_off [N_NODES];
__device__ int    g_cur [N_NODES];
__device__ int    g_pack[N_EDGES];                  // (et<<17)|src
__device__ int    g_part [NBLK_SCAN];
__device__ int    g_partx[NBLK_SCAN];
__device__ int    g_idx64;

// ---------------------------------------------------------------------------
// Helpers
// ---------------------------------------------------------------------------
typedef unsigned long long u64;

__device__ __forceinline__ u64 pack2(float lo, float hi) {
    u64 r; asm("mov.b64 %0, {%1, %2};" : "=l"(r) : "f"(lo), "f"(hi)); return r;
}
__device__ __forceinline__ u64 dup2(float v) {
    u64 r; asm("mov.b64 %0, {%1, %1};" : "=l"(r) : "f"(v)); return r;
}
__device__ __forceinline__ void fma2(u64& acc, u64 a, u64 b) {
    asm("fma.rn.f32x2 %0, %1, %2, %0;" : "+l"(acc) : "l"(a), "l"(b));
}
__device__ __forceinline__ float2 unpack2(u64 v) {
    float lo, hi; asm("mov.b64 {%0, %1}, %2;" : "=f"(lo), "=f"(hi) : "l"(v));
    return make_float2(lo, hi);
}
__device__ __forceinline__ uint32_t smem_u32(const void* p) {
    uint32_t a;
    asm("{ .reg .u64 t; cvta.to.shared.u64 t, %1; cvt.u32.u64 %0, t; }"
        : "=r"(a) : "l"(p));
    return a;
}
__device__ __forceinline__ void ldm_x4(uint32_t& r0, uint32_t& r1,
                                       uint32_t& r2, uint32_t& r3, uint32_t addr) {
    asm volatile("ldmatrix.sync.aligned.m8n8.x4.shared.b16 {%0,%1,%2,%3}, [%4];"
                 : "=r"(r0), "=r"(r1), "=r"(r2), "=r"(r3) : "r"(addr));
}
__device__ __forceinline__ void ldm_x4_t(uint32_t& r0, uint32_t& r1,
                                         uint32_t& r2, uint32_t& r3, uint32_t addr) {
    asm volatile("ldmatrix.sync.aligned.m8n8.x4.trans.shared.b16 {%0,%1,%2,%3}, [%4];"
                 : "=r"(r0), "=r"(r1), "=r"(r2), "=r"(r3) : "r"(addr));
}
__device__ __forceinline__ void mma_f16(float* c,
                                        uint32_t a0, uint32_t a1, uint32_t a2, uint32_t a3,
                                        uint32_t b0, uint32_t b1) {
    asm volatile("mma.sync.aligned.m16n8k16.row.col.f32.f16.f16.f32 "
                 "{%0,%1,%2,%3}, {%4,%5,%6,%7}, {%8,%9}, {%0,%1,%2,%3};"
                 : "+f"(c[0]), "+f"(c[1]), "+f"(c[2]), "+f"(c[3])
                 : "r"(a0), "r"(a1), "r"(a2), "r"(a3), "r"(b0), "r"(b1));
}

// ---------------------------------------------------------------------------
// Probe: int64 vs int32 indices (parallel: 1024 loads, 1 block)
// ---------------------------------------------------------------------------
__global__ void probe_kernel(const void* src) {
    __shared__ int bad;
    if (threadIdx.x == 0) bad = 0;
    __syncthreads();
    long long v = ((const long long*)src)[threadIdx.x];
    if (v < 0 || v >= (long long)N_NODES) bad = 1;
    __syncthreads();
    if (threadIdx.x == 0) g_idx64 = bad ? 0 : 1;
}

__device__ __forceinline__ int load_idx(const void* p, int e, int idx64) {
    return idx64 ? (int)((const long long*)p)[e] : ((const int*)p)[e];
}

// ---------------------------------------------------------------------------
// B[k][n] = fp16(weight flat [b][kin][o]) — already k-major, plain convert.
// ---------------------------------------------------------------------------
__global__ __launch_bounds__(256) void prep_bt(const float* __restrict__ weight) {
    int idx = blockIdx.x * 256 + threadIdx.x;       // 1024*128 = 131072
    if (idx >= KTOT * FEAT) return;
    g_bth[idx] = __float2half(weight[idx]);
}

// ---------------------------------------------------------------------------
// CSR build
// ---------------------------------------------------------------------------
__global__ __launch_bounds__(256) void zero_deg() {
    int i = blockIdx.x * 256 + threadIdx.x;
    if (i < N_NODES) g_deg[i] = 0;
}

__global__ __launch_bounds__(256) void count_deg(const void* dstp) {
    int e = blockIdx.x * 256 + threadIdx.x;
    if (e >= N_EDGES) return;
    int d = load_idx(dstp, e, g_idx64);
    atomicAdd(&g_deg[d], 1);
}

__global__ __launch_bounds__(256) void scan1() {
    __shared__ int wsum[8];
    int t = threadIdx.x, blk = blockIdx.x;
    int i0 = blk * 512 + 2 * t, i1 = i0 + 1;
    int s = (i0 < N_NODES ? g_deg[i0] : 0) + (i1 < N_NODES ? g_deg[i1] : 0);
#pragma unroll
    for (int o = 16; o > 0; o >>= 1) s += __shfl_down_sync(0xffffffffu, s, o);
    if ((t & 31) == 0) wsum[t >> 5] = s;
    __syncthreads();
    if (t == 0) {
        int tot = 0;
#pragma unroll
        for (int w = 0; w < 8; w++) tot += wsum[w];
        g_part[blk] = tot;
    }
}

__global__ __launch_bounds__(256) void scan2() {
    __shared__ int sh[256];
    int t = threadIdx.x;
    int v = (t < NBLK_SCAN) ? g_part[t] : 0;
    int orig = v;
    sh[t] = v;
    __syncthreads();
    for (int o = 1; o < 256; o <<= 1) {
        int u = (t >= o) ? sh[t - o] : 0;
        __syncthreads();
        sh[t] += u;
        __syncthreads();
    }
    if (t < NBLK_SCAN) g_partx[t] = sh[t] - orig;
}

__global__ __launch_bounds__(256) void scan3() {
    __shared__ int wsum[8], woff[8];
    int t = threadIdx.x, blk = blockIdx.x;
    int lane = t & 31, wid = t >> 5;
    int i0 = blk * 512 + 2 * t, i1 = i0 + 1;
    int d0 = (i0 < N_NODES ? g_deg[i0] : 0);
    int d1 = (i1 < N_NODES ? g_deg[i1] : 0);
    int s = d0 + d1;
    int v = s;
#pragma unroll
    for (int o = 1; o < 32; o <<= 1) {
        int u = __shfl_up_sync(0xffffffffu, v, o);
        if (lane >= o) v += u;
    }
    if (lane == 31) wsum[wid] = v;
    __syncthreads();
    if (t < 8) {
        int p = 0;
        for (int j = 0; j < t; j++) p += wsum[j];
        woff[t] = p;
    }
    __syncthreads();
    int excl = v - s + woff[wid] + g_partx[blk];
    if (i0 < N_NODES) { g_off[i0] = excl;      g_cur[i0] = excl;      }
    if (i1 < N_NODES) { g_off[i1] = excl + d0; g_cur[i1] = excl + d0; }
}

__global__ __launch_bounds__(256) void fill_csr(const void* srcp,
                                                const void* dstp,
                                                const void* etp) {
    int e = blockIdx.x * 256 + threadIdx.x;
    if (e >= N_EDGES) return;
    int idx64 = g_idx64;
    int s  = load_idx(srcp, e, idx64);
    int d  = load_idx(dstp, e, idx64);
    int et = load_idx(etp,  e, idx64);
    int pos = atomicAdd(&g_cur[d], 1);
    g_pack[pos] = (et << 17) | s;
}

// ---------------------------------------------------------------------------
// Aggregate: one warp per dst node; f32x2 accumulate; fp16-round on store.
// ---------------------------------------------------------------------------
__global__ __launch_bounds__(256) void aggregate(const float* __restrict__ x,
                                                 const float* __restrict__ w_comp) {
    __shared__ float cw[NUM_RELS * NUM_BASES];
    if (threadIdx.x < NUM_RELS * NUM_BASES)
        cw[threadIdx.x] = w_comp[threadIdx.x];
    __syncthreads();

    const int node = blockIdx.x * 8 + (threadIdx.x >> 5);
    const int lane = threadIdx.x & 31;
    if (node >= N_NODES) return;

    const int beg = g_off[node];
    const int cnt = g_deg[node];
    const float4* x4 = (const float4*)x;

    u64 acc[NUM_BASES][2];
#pragma unroll
    for (int b = 0; b < NUM_BASES; b++) { acc[b][0] = 0ull; acc[b][1] = 0ull; }

    for (int b0 = 0; b0 < cnt; b0 += 32) {
        int pk = (b0 + lane < cnt) ? g_pack[beg + b0 + lane] : 0;
        int m = cnt - b0;
        if (m > 32) m = 32;
#pragma unroll 4
        for (int j = 0; j < m; j++) {
            int p = __shfl_sync(0xffffffffu, pk, j);
            int src = p & 0x1FFFF;
            int et  = p >> 17;
            float4 xv = x4[(size_t)src * 32 + lane];
            u64 xlo = pack2(xv.x, xv.y);
            u64 xhi = pack2(xv.z, xv.w);
#pragma unroll
            for (int b = 0; b < NUM_BASES; b++) {
                u64 c2 = dup2(cw[et * NUM_BASES + b]);
                fma2(acc[b][0], c2, xlo);
                fma2(acc[b][1], c2, xhi);
            }
        }
    }

    __half* ag = g_aggh + (size_t)node * KTOT + lane * 4;
#pragma unroll
    for (int b = 0; b < NUM_BASES; b++) {
        float2 lo = unpack2(acc[b][0]);
        float2 hi = unpack2(acc[b][1]);
        __half2 h01 = __floats2half2_rn(lo.x, lo.y);
        __half2 h23 = __floats2half2_rn(hi.x, hi.y);
        uint2 v;
        v.x = *(uint32_t*)&h01;
        v.y = *(uint32_t*)&h23;
        __stcs((uint2*)(ag + b * FEAT), v);
    }
}

// ---------------------------------------------------------------------------
// out[100000 x 128] = aggh[100000 x 1024] @ B + bias  via fp16 mma m16n8k16.
// BM=128, BN=128, BK=32; 256 thr = 8 warps (4M x 2N); warp tile 32x64.
// A SMEM: [128 rows][pitch 40 halves]; B SMEM: [32 k-rows][pitch 136 halves].
// Fragments via ldmatrix.x4 (A) / ldmatrix.x4.trans (B) — conflict-free pads.
// ---------------------------------------------------------------------------
#define PA 40
#define PB 136
#define NKIT (KTOT / 32)

__global__ __launch_bounds__(256, 2) void out_gemm(const float* __restrict__ bias,
                                                   float* __restrict__ out) {
    __shared__ __align__(16) __half Ash[128 * PA];   // 10240 B
    __shared__ __align__(16) __half Bsh[32 * PB];    // 8704 B
    __shared__ float bsm[128];

    const int tid    = threadIdx.x;
    const int wid    = tid >> 5;
    const int lane   = tid & 31;
    const int warp_m = wid & 3;
    const int warp_n = wid >> 2;
    const int grp    = lane >> 2;
    const int tig    = lane & 3;
    const int quad   = lane >> 3;     // 0..3 (ldmatrix matrix select)
    const int qi     = lane & 7;      // 0..7 (row within matrix)
    const int m0     = blockIdx.x * 128;

    if (tid < 128) bsm[tid] = bias[tid];

    float acc[2][8][4];
#pragma unroll
    for (int i = 0; i < 2; i++)
#pragma unroll
        for (int j = 0; j < 8; j++)
#pragma unroll
            for (int q = 0; q < 4; q++) acc[i][j][q] = 0.f;

    // Staging assignments
    const int a_row = tid >> 1;             // 0..127
    const int a_hc  = (tid & 1) * 16;       // half-offset 0 or 16
    const bool aok  = (m0 + a_row) < N_NODES;
    const __half* agp = g_aggh + (size_t)(m0 + a_row) * KTOT + a_hc;
    const int b_row = tid >> 3;             // 0..31
    const int b_nc  = (tid & 7) * 16;
    const __half* bgp = g_bth + (size_t)b_row * FEAT + b_nc;

    // ldmatrix per-thread address components
    const uint32_t asb = smem_u32(Ash);
    const uint32_t bsb = smem_u32(Bsh);
    const int a_mrow = (quad & 1) * 8 + qi;      // row within 16-row subtile
    const int a_koff = (quad >> 1) * 8;          // 0 or 8
    const int b_koff = (quad & 1) * 8 + qi;      // k-row within 16
    const int b_noff = (quad >> 1) * 8;          // 0 or 8

    for (int kk = 0; kk < KTOT; kk += 32) {
        __syncthreads();
        // ---- Stage A: 16 halves (32 B) per thread ----
        if (aok) {
            uint4 v0 = *(const uint4*)(agp + kk);
            uint4 v1 = *(const uint4*)(agp + kk + 8);
            *(uint4*)(Ash + a_row * PA + a_hc)     = v0;
            *(uint4*)(Ash + a_row * PA + a_hc + 8) = v1;
        } else {
            uint4 z = make_uint4(0u, 0u, 0u, 0u);
            *(uint4*)(Ash + a_row * PA + a_hc)     = z;
            *(uint4*)(Ash + a_row * PA + a_hc + 8) = z;
        }
        // ---- Stage B: 16 halves per thread ----
        {
            uint4 v0 = *(const uint4*)(bgp + (size_t)kk * FEAT);
            uint4 v1 = *(const uint4*)(bgp + (size_t)kk * FEAT + 8);
            *(uint4*)(Bsh + b_row * PB + b_nc)     = v0;
            *(uint4*)(Bsh + b_row * PB + b_nc + 8) = v1;
        }
        __syncthreads();

#pragma unroll
        for (int ks = 0; ks < 2; ks++) {
            uint32_t af[2][4];
#pragma unroll
            for (int i = 0; i < 2; i++) {
                uint32_t ad = asb + (uint32_t)((warp_m * 32 + i * 16 + a_mrow) * PA
                                               + ks * 16 + a_koff) * 2u;
                ldm_x4(af[i][0], af[i][1], af[i][2], af[i][3], ad);
            }
            uint32_t bf[4][4];   // [j-pair][r]: r0,r1 = col 2p; r2,r3 = col 2p+1
#pragma unroll
            for (int p = 0; p < 4; p++) {
                uint32_t bd = bsb + (uint32_t)((ks * 16 + b_koff) * PB
                                               + warp_n * 64 + p * 16 + b_noff) * 2u;
                ldm_x4_t(bf[p][0], bf[p][1], bf[p][2], bf[p][3], bd);
            }
#pragma unroll
            for (int i = 0; i < 2; i++)
#pragma unroll
                for (int j = 0; j < 8; j++) {
                    const uint32_t* bp = bf[j >> 1];
                    uint32_t b0 = (j & 1) ? bp[2] : bp[0];
                    uint32_t b1 = (j & 1) ? bp[3] : bp[1];
                    mma_f16(acc[i][j], af[i][0], af[i][1], af[i][2], af[i][3], b0, b1);
                }
        }
    }

#pragma unroll
    for (int i = 0; i < 2; i++) {
        int row_lo = m0 + warp_m * 32 + i * 16 + grp;
        int row_hi = row_lo + 8;
#pragma unroll
        for (int j = 0; j < 8; j++) {
            int col = warp_n * 64 + j * 8 + 2 * tig;
            if (row_lo < N_NODES)
                *(float2*)(out + (size_t)row_lo * FEAT + col) =
                    make_float2(acc[i][j][0] + bsm[col],
                                acc[i][j][1] + bsm[col + 1]);
            if (row_hi < N_NODES)
                *(float2*)(out + (size_t)row_hi * FEAT + col) =
                    make_float2(acc[i][j][2] + bsm[col],
                                acc[i][j][3] + bsm[col + 1]);
        }
    }
}

// ---------------------------------------------------------------------------
// Launch
// ---------------------------------------------------------------------------
extern "C" void kernel_launch(void* const* d_in, const int* in_sizes, int n_in,
                              void* d_out, int out_size) {
    const float* x      = (const float*)d_in[0];
    const float* weight = (const float*)d_in[1];
    const float* w_comp = (const float*)d_in[2];
    const float* h_bias = (const float*)d_in[3];
    const void*  src    = d_in[4];
    const void*  dst    = d_in[5];
    const void*  etyp   = d_in[6];
    float*       out    = (float*)d_out;

    probe_kernel<<<1, 1024>>>(src);
    prep_bt<<<(KTOT * FEAT + 255) / 256, 256>>>(weight);

    // CSR by destination
    zero_deg<<<(N_NODES + 255) / 256, 256>>>();
    count_deg<<<(N_EDGES + 255) / 256, 256>>>(dst);
    scan1<<<NBLK_SCAN, 256>>>();
    scan2<<<1, 256>>>();
    scan3<<<NBLK_SCAN, 256>>>();
    fill_csr<<<(N_EDGES + 255) / 256, 256>>>(src, dst, etyp);

    // Basis-weighted aggregation (fp16 output)
    aggregate<<<(N_NODES + 7) / 8, 256>>>(x, w_comp);

    // Fused transform + bias (fp16 tensor-core GEMM)
    out_gemm<<<(N_NODES + 127) / 128, 256>>>(h_bias, out);
}

// round 13
// speedup vs baseline: 1.3536x; 1.0253x over previous
#include <cuda_runtime.h>
#include <cuda_fp16.h>
#include <cstdint>
#include <cstddef>

#define N_NODES  100000
#define N_EDGES  3200000
#define FEAT     128
#define NUM_RELS 16
#define NUM_BASES 8
#define KTOT     (NUM_BASES * FEAT)   // 1024

#define NBLK_SCAN 196                 // 196 * 512 = 100352 >= N_NODES

// Scratch (static device globals — no runtime allocation allowed).
__device__ __half g_aggh[(size_t)N_NODES * KTOT];   // 205 MB: agg[d][b*128+k], fp16
__device__ __half g_xh  [(size_t)N_NODES * FEAT];   // 25.6 MB: x in fp16 (L2-resident)
__device__ __half g_bth [(size_t)KTOT * FEAT];      // 256 KB: B[k][n] = weight flat, fp16
__device__ int    g_deg [N_NODES];
__device__ int    g_off [N_NODES];
__device__ int    g_cur [N_NODES];
__device__ int    g_pack[N_EDGES];                  // (et<<17)|src
__device__ int    g_part [NBLK_SCAN];
__device__ int    g_partx[NBLK_SCAN];
__device__ int    g_idx64;

// ---------------------------------------------------------------------------
// Helpers
// ---------------------------------------------------------------------------
typedef unsigned long long u64;

__device__ __forceinline__ u64 pack2(float lo, float hi) {
    u64 r; asm("mov.b64 %0, {%1, %2};" : "=l"(r) : "f"(lo), "f"(hi)); return r;
}
__device__ __forceinline__ u64 dup2(float v) {
    u64 r; asm("mov.b64 %0, {%1, %1};" : "=l"(r) : "f"(v)); return r;
}
__device__ __forceinline__ void fma2(u64& acc, u64 a, u64 b) {
    asm("fma.rn.f32x2 %0, %1, %2, %0;" : "+l"(acc) : "l"(a), "l"(b));
}
__device__ __forceinline__ float2 unpack2(u64 v) {
    float lo, hi; asm("mov.b64 {%0, %1}, %2;" : "=f"(lo), "=f"(hi) : "l"(v));
    return make_float2(lo, hi);
}
__device__ __forceinline__ uint32_t smem_u32(const void* p) {
    uint32_t a;
    asm("{ .reg .u64 t; cvta.to.shared.u64 t, %1; cvt.u32.u64 %0, t; }"
        : "=r"(a) : "l"(p));
    return a;
}
__device__ __forceinline__ void ldm_x4(uint32_t& r0, uint32_t& r1,
                                       uint32_t& r2, uint32_t& r3, uint32_t addr) {
    asm volatile("ldmatrix.sync.aligned.m8n8.x4.shared.b16 {%0,%1,%2,%3}, [%4];"
                 : "=r"(r0), "=r"(r1), "=r"(r2), "=r"(r3) : "r"(addr));
}
__device__ __forceinline__ void ldm_x4_t(uint32_t& r0, uint32_t& r1,
                                         uint32_t& r2, uint32_t& r3, uint32_t addr) {
    asm volatile("ldmatrix.sync.aligned.m8n8.x4.trans.shared.b16 {%0,%1,%2,%3}, [%4];"
                 : "=r"(r0), "=r"(r1), "=r"(r2), "=r"(r3) : "r"(addr));
}
__device__ __forceinline__ void mma_f16(float* c,
                                        uint32_t a0, uint32_t a1, uint32_t a2, uint32_t a3,
                                        uint32_t b0, uint32_t b1) {
    asm volatile("mma.sync.aligned.m16n8k16.row.col.f32.f16.f16.f32 "
                 "{%0,%1,%2,%3}, {%4,%5,%6,%7}, {%8,%9}, {%0,%1,%2,%3};"
                 : "+f"(c[0]), "+f"(c[1]), "+f"(c[2]), "+f"(c[3])
                 : "r"(a0), "r"(a1), "r"(a2), "r"(a3), "r"(b0), "r"(b1));
}

// ---------------------------------------------------------------------------
// Probe: int64 vs int32 indices (parallel: 1024 loads, 1 block)
// ---------------------------------------------------------------------------
__global__ void probe_kernel(const void* src) {
    __shared__ int bad;
    if (threadIdx.x == 0) bad = 0;
    __syncthreads();
    long long v = ((const long long*)src)[threadIdx.x];
    if (v < 0 || v >= (long long)N_NODES) bad = 1;
    __syncthreads();
    if (threadIdx.x == 0) g_idx64 = bad ? 0 : 1;
}

__device__ __forceinline__ int load_idx(const void* p, int e, int idx64) {
    return idx64 ? (int)((const long long*)p)[e] : ((const int*)p)[e];
}

// ---------------------------------------------------------------------------
// Prep: B[k][n] = fp16(weight flat), x -> fp16
// ---------------------------------------------------------------------------
__global__ __launch_bounds__(256) void prep_bt(const float* __restrict__ weight) {
    int idx = blockIdx.x * 256 + threadIdx.x;       // 1024*128 = 131072
    if (idx >= KTOT * FEAT) return;
    g_bth[idx] = __float2half(weight[idx]);
}

__global__ __launch_bounds__(256) void prep_x(const float* __restrict__ x) {
    size_t idx = ((size_t)blockIdx.x * 256 + threadIdx.x) * 4;
    if (idx >= (size_t)N_NODES * FEAT) return;
    float4 v = *(const float4*)(x + idx);
    __half2 h01 = __floats2half2_rn(v.x, v.y);
    __half2 h23 = __floats2half2_rn(v.z, v.w);
    uint2 o;
    o.x = *(uint32_t*)&h01;
    o.y = *(uint32_t*)&h23;
    *(uint2*)(g_xh + idx) = o;
}

// ---------------------------------------------------------------------------
// CSR build
// ---------------------------------------------------------------------------
__global__ __launch_bounds__(256) void zero_deg() {
    int i = blockIdx.x * 256 + threadIdx.x;
    if (i < N_NODES) g_deg[i] = 0;
}

__global__ __launch_bounds__(256) void count_deg(const void* dstp) {
    int e = blockIdx.x * 256 + threadIdx.x;
    if (e >= N_EDGES) return;
    int d = load_idx(dstp, e, g_idx64);
    atomicAdd(&g_deg[d], 1);
}

__global__ __launch_bounds__(256) void scan1() {
    __shared__ int wsum[8];
    int t = threadIdx.x, blk = blockIdx.x;
    int i0 = blk * 512 + 2 * t, i1 = i0 + 1;
    int s = (i0 < N_NODES ? g_deg[i0] : 0) + (i1 < N_NODES ? g_deg[i1] : 0);
#pragma unroll
    for (int o = 16; o > 0; o >>= 1) s += __shfl_down_sync(0xffffffffu, s, o);
    if ((t & 31) == 0) wsum[t >> 5] = s;
    __syncthreads();
    if (t == 0) {
        int tot = 0;
#pragma unroll
        for (int w = 0; w < 8; w++) tot += wsum[w];
        g_part[blk] = tot;
    }
}

__global__ __launch_bounds__(256) void scan2() {
    __shared__ int sh[256];
    int t = threadIdx.x;
    int v = (t < NBLK_SCAN) ? g_part[t] : 0;
    int orig = v;
    sh[t] = v;
    __syncthreads();
    for (int o = 1; o < 256; o <<= 1) {
        int u = (t >= o) ? sh[t - o] : 0;
        __syncthreads();
        sh[t] += u;
        __syncthreads();
    }
    if (t < NBLK_SCAN) g_partx[t] = sh[t] - orig;
}

__global__ __launch_bounds__(256) void scan3() {
    __shared__ int wsum[8], woff[8];
    int t = threadIdx.x, blk = blockIdx.x;
    int lane = t & 31, wid = t >> 5;
    int i0 = blk * 512 + 2 * t, i1 = i0 + 1;
    int d0 = (i0 < N_NODES ? g_deg[i0] : 0);
    int d1 = (i1 < N_NODES ? g_deg[i1] : 0);
    int s = d0 + d1;
    int v = s;
#pragma unroll
    for (int o = 1; o < 32; o <<= 1) {
        int u = __shfl_up_sync(0xffffffffu, v, o);
        if (lane >= o) v += u;
    }
    if (lane == 31) wsum[wid] = v;
    __syncthreads();
    if (t < 8) {
        int p = 0;
        for (int j = 0; j < t; j++) p += wsum[j];
        woff[t] = p;
    }
    __syncthreads();
    int excl = v - s + woff[wid] + g_partx[blk];
    if (i0 < N_NODES) { g_off[i0] = excl;      g_cur[i0] = excl;      }
    if (i1 < N_NODES) { g_off[i1] = excl + d0; g_cur[i1] = excl + d0; }
}

__global__ __launch_bounds__(256) void fill_csr(const void* srcp,
                                                const void* dstp,
                                                const void* etp) {
    int e = blockIdx.x * 256 + threadIdx.x;
    if (e >= N_EDGES) return;
    int idx64 = g_idx64;
    int s  = load_idx(srcp, e, idx64);
    int d  = load_idx(dstp, e, idx64);
    int et = load_idx(etp,  e, idx64);
    int pos = atomicAdd(&g_cur[d], 1);
    g_pack[pos] = (et << 17) | s;
}

// ---------------------------------------------------------------------------
// Aggregate: one warp per dst node; fp16 x gather (halved L2 traffic),
// f32x2 accumulate; fp16-round on store.
// ---------------------------------------------------------------------------
__global__ __launch_bounds__(256) void aggregate(const float* __restrict__ w_comp) {
    __shared__ float cw[NUM_RELS * NUM_BASES];
    if (threadIdx.x < NUM_RELS * NUM_BASES)
        cw[threadIdx.x] = w_comp[threadIdx.x];
    __syncthreads();

    const int node = blockIdx.x * 8 + (threadIdx.x >> 5);
    const int lane = threadIdx.x & 31;
    if (node >= N_NODES) return;

    const int beg = g_off[node];
    const int cnt = g_deg[node];
    const uint2* x2 = (const uint2*)g_xh;   // 32 uint2 per 128-half row

    u64 acc[NUM_BASES][2];
#pragma unroll
    for (int b = 0; b < NUM_BASES; b++) { acc[b][0] = 0ull; acc[b][1] = 0ull; }

    for (int b0 = 0; b0 < cnt; b0 += 32) {
        int pk = (b0 + lane < cnt) ? g_pack[beg + b0 + lane] : 0;
        int m = cnt - b0;
        if (m > 32) m = 32;
#pragma unroll 4
        for (int j = 0; j < m; j++) {
            int p = __shfl_sync(0xffffffffu, pk, j);
            int src = p & 0x1FFFF;
            int et  = p >> 17;
            uint2 xv = x2[(size_t)src * 32 + lane];
            float2 f01 = __half22float2(*(__half2*)&xv.x);
            float2 f23 = __half22float2(*(__half2*)&xv.y);
            u64 xlo = pack2(f01.x, f01.y);
            u64 xhi = pack2(f23.x, f23.y);
#pragma unroll
            for (int b = 0; b < NUM_BASES; b++) {
                u64 c2 = dup2(cw[et * NUM_BASES + b]);
                fma2(acc[b][0], c2, xlo);
                fma2(acc[b][1], c2, xhi);
            }
        }
    }

    __half* ag = g_aggh + (size_t)node * KTOT + lane * 4;
#pragma unroll
    for (int b = 0; b < NUM_BASES; b++) {
        float2 lo = unpack2(acc[b][0]);
        float2 hi = unpack2(acc[b][1]);
        __half2 h01 = __floats2half2_rn(lo.x, lo.y);
        __half2 h23 = __floats2half2_rn(hi.x, hi.y);
        uint2 v;
        v.x = *(uint32_t*)&h01;
        v.y = *(uint32_t*)&h23;
        __stcs((uint2*)(ag + b * FEAT), v);
    }
}

// ---------------------------------------------------------------------------
// out[100000 x 128] = aggh[100000 x 1024] @ B + bias  via fp16 mma m16n8k16.
// BM=128, BN=128, BK=32; 256 thr = 8 warps (4M x 2N); warp tile 32x64.
// A SMEM: [128 rows][pitch 40 halves]; B SMEM: [32 k-rows][pitch 136 halves].
// Fragments via ldmatrix.x4 (A) / ldmatrix.x4.trans (B) — conflict-free pads.
// ---------------------------------------------------------------------------
#define PA 40
#define PB 136
#define NKIT (KTOT / 32)

__global__ __launch_bounds__(256, 2) void out_gemm(const float* __restrict__ bias,
                                                   float* __restrict__ out) {
    __shared__ __align__(16) __half Ash[128 * PA];   // 10240 B
    __shared__ __align__(16) __half Bsh[32 * PB];    // 8704 B
    __shared__ float bsm[128];

    const int tid    = threadIdx.x;
    const int wid    = tid >> 5;
    const int lane   = tid & 31;
    const int warp_m = wid & 3;
    const int warp_n = wid >> 2;
    const int grp    = lane >> 2;
    const int tig    = lane & 3;
    const int quad   = lane >> 3;     // 0..3 (ldmatrix matrix select)
    const int qi     = lane & 7;      // 0..7 (row within matrix)
    const int m0     = blockIdx.x * 128;

    if (tid < 128) bsm[tid] = bias[tid];

    float acc[2][8][4];
#pragma unroll
    for (int i = 0; i < 2; i++)
#pragma unroll
        for (int j = 0; j < 8; j++)
#pragma unroll
            for (int q = 0; q < 4; q++) acc[i][j][q] = 0.f;

    // Staging assignments
    const int a_row = tid >> 1;             // 0..127
    const int a_hc  = (tid & 1) * 16;       // half-offset 0 or 16
    const bool aok  = (m0 + a_row) < N_NODES;
    const __half* agp = g_aggh + (size_t)(m0 + a_row) * KTOT + a_hc;
    const int b_row = tid >> 3;             // 0..31
    const int b_nc  = (tid & 7) * 16;
    const __half* bgp = g_bth + (size_t)b_row * FEAT + b_nc;

    // ldmatrix per-thread address components
    const uint32_t asb = smem_u32(Ash);
    const uint32_t bsb = smem_u32(Bsh);
    const int a_mrow = (quad & 1) * 8 + qi;      // row within 16-row subtile
    const int a_koff = (quad >> 1) * 8;          // 0 or 8
    const int b_koff = (quad & 1) * 8 + qi;      // k-row within 16
    const int b_noff = (quad >> 1) * 8;          // 0 or 8

    for (int kk = 0; kk < KTOT; kk += 32) {
        __syncthreads();
        // ---- Stage A: 16 halves (32 B) per thread ----
        if (aok) {
            uint4 v0 = *(const uint4*)(agp + kk);
            uint4 v1 = *(const uint4*)(agp + kk + 8);
            *(uint4*)(Ash + a_row * PA + a_hc)     = v0;
            *(uint4*)(Ash + a_row * PA + a_hc + 8) = v1;
        } else {
            uint4 z = make_uint4(0u, 0u, 0u, 0u);
            *(uint4*)(Ash + a_row * PA + a_hc)     = z;
            *(uint4*)(Ash + a_row * PA + a_hc + 8) = z;
        }
        // ---- Stage B: 16 halves per thread ----
        {
            uint4 v0 = *(const uint4*)(bgp + (size_t)kk * FEAT);
            uint4 v1 = *(const uint4*)(bgp + (size_t)kk * FEAT + 8);
            *(uint4*)(Bsh + b_row * PB + b_nc)     = v0;
            *(uint4*)(Bsh + b_row * PB + b_nc + 8) = v1;
        }
        __syncthreads();

#pragma unroll
        for (int ks = 0; ks < 2; ks++) {
            uint32_t af[2][4];
#pragma unroll
            for (int i = 0; i < 2; i++) {
                uint32_t ad = asb + (uint32_t)((warp_m * 32 + i * 16 + a_mrow) * PA
                                               + ks * 16 + a_koff) * 2u;
                ldm_x4(af[i][0], af[i][1], af[i][2], af[i][3], ad);
            }
            uint32_t bf[4][4];   // [j-pair][r]: r0,r1 = col 2p; r2,r3 = col 2p+1
#pragma unroll
            for (int p = 0; p < 4; p++) {
                uint32_t bd = bsb + (uint32_t)((ks * 16 + b_koff) * PB
                                               + warp_n * 64 + p * 16 + b_noff) * 2u;
                ldm_x4_t(bf[p][0], bf[p][1], bf[p][2], bf[p][3], bd);
            }
#pragma unroll
            for (int i = 0; i < 2; i++)
#pragma unroll
                for (int j = 0; j < 8; j++) {
                    const uint32_t* bp = bf[j >> 1];
                    uint32_t b0 = (j & 1) ? bp[2] : bp[0];
                    uint32_t b1 = (j & 1) ? bp[3] : bp[1];
                    mma_f16(acc[i][j], af[i][0], af[i][1], af[i][2], af[i][3], b0, b1);
                }
        }
    }

#pragma unroll
    for (int i = 0; i < 2; i++) {
        int row_lo = m0 + warp_m * 32 + i * 16 + grp;
        int row_hi = row_lo + 8;
#pragma unroll
        for (int j = 0; j < 8; j++) {
            int col = warp_n * 64 + j * 8 + 2 * tig;
            if (row_lo < N_NODES)
                *(float2*)(out + (size_t)row_lo * FEAT + col) =
                    make_float2(acc[i][j][0] + bsm[col],
                                acc[i][j][1] + bsm[col + 1]);
            if (row_hi < N_NODES)
                *(float2*)(out + (size_t)row_hi * FEAT + col) =
                    make_float2(acc[i][j][2] + bsm[col],
                                acc[i][j][3] + bsm[col + 1]);
        }
    }
}

// ---------------------------------------------------------------------------
// Launch
// ---------------------------------------------------------------------------
extern "C" void kernel_launch(void* const* d_in, const int* in_sizes, int n_in,
                              void* d_out, int out_size) {
    const float* x      = (const float*)d_in[0];
    const float* weight = (const float*)d_in[1];
    const float* w_comp = (const float*)d_in[2];
    const float* h_bias = (const float*)d_in[3];
    const void*  src    = d_in[4];
    const void*  dst    = d_in[5];
    const void*  etyp   = d_in[6];
    float*       out    = (float*)d_out;

    probe_kernel<<<1, 1024>>>(src);
    prep_bt<<<(KTOT * FEAT + 255) / 256, 256>>>(weight);
    prep_x<<<(N_NODES * FEAT / 4 + 255) / 256, 256>>>(x);

    // CSR by destination
    zero_deg<<<(N_NODES + 255) / 256, 256>>>();
    count_deg<<<(N_EDGES + 255) / 256, 256>>>(dst);
    scan1<<<NBLK_SCAN, 256>>>();
    scan2<<<1, 256>>>();
    scan3<<<NBLK_SCAN, 256>>>();
    fill_csr<<<(N_EDGES + 255) / 256, 256>>>(src, dst, etyp);

    // Basis-weighted aggregation (fp16 x gather, fp32 accumulate, fp16 store)
    aggregate<<<(N_NODES + 7) / 8, 256>>>(w_comp);

    // Fused transform + bias (fp16 tensor-core GEMM)
    out_gemm<<<(N_NODES + 127) / 128, 256>>>(h_bias, out);
}